// round 1
// baseline (speedup 1.0000x reference)
#include <cuda_runtime.h>
#include <math.h>

#define Bsz  4
#define NN   32
#define EMB  512
#define FEAT 512
#define DOP  496
#define BD   (Bsz*DOP)   // 1984

// output layout: concatenation of (X_raw, X_do, label, causal_graph, e, s)
#define OFF_XRAW 0
#define OFF_XDO  65536
#define OFF_LBL  32571392
#define OFF_CG   34603008
#define OFF_E    34607104
#define OFF_S    34611200

// scratch (no allocations allowed -> __device__ globals)
__device__ float    g_feat [Bsz*NN*FEAT];
__device__ float    g_fU   [Bsz*NN*FEAT];
__device__ float    g_featD[Bsz*NN*FEAT];
__device__ float    g_part [4*128*512];
__device__ float    g_attn [Bsz*NN*NN];
__device__ float    g_Wmain[Bsz*NN*NN];
__device__ unsigned g_posmask[Bsz*NN];
__device__ unsigned g_commonmask[Bsz*NN];

// ---------------------------------------------------------------------------
// C(128x512) = A(128x512) @ Bm(512x512), split-K into 4 chunks of 128.
// grid (8 ct, 4 rt, 4 kc), 256 threads. Tile 32x64 per block.
// mode 0: A = Aext (doc_sents_h) ; mode 1: A = g_fU
// ---------------------------------------------------------------------------
__global__ __launch_bounds__(256) void gemm_part_kernel(
    const float* __restrict__ Aext, const float* __restrict__ Bm, int mode)
{
    __shared__ float As[32][129];
    __shared__ float Bs[128][64];
    const float* A = mode ? g_fU : Aext;
    int ct = blockIdx.x, rt = blockIdx.y, kc = blockIdx.z;
    int t = threadIdx.x;

    #pragma unroll
    for (int it = 0; it < 4; ++it) {
        int l = (t + 256*it) * 4;
        int r = l >> 7, c = l & 127;
        float4 v = *reinterpret_cast<const float4*>(A + (rt*32 + r)*512 + kc*128 + c);
        As[r][c] = v.x; As[r][c+1] = v.y; As[r][c+2] = v.z; As[r][c+3] = v.w;
    }
    #pragma unroll
    for (int it = 0; it < 8; ++it) {
        int l4 = t + 256*it;
        int kk = l4 >> 4, c4 = l4 & 15;
        *reinterpret_cast<float4*>(&Bs[kk][c4*4]) =
            *reinterpret_cast<const float4*>(Bm + (kc*128 + kk)*512 + ct*64 + c4*4);
    }
    __syncthreads();

    int c4 = t & 15, r2 = t >> 4;
    int i0 = r2*2, j0 = c4*4;
    float a00=0,a01=0,a02=0,a03=0,a10=0,a11=0,a12=0,a13=0;
    #pragma unroll 4
    for (int kk = 0; kk < 128; ++kk) {
        float4 bv = *reinterpret_cast<const float4*>(&Bs[kk][j0]);
        float x0 = As[i0][kk], x1 = As[i0+1][kk];
        a00 += x0*bv.x; a01 += x0*bv.y; a02 += x0*bv.z; a03 += x0*bv.w;
        a10 += x1*bv.x; a11 += x1*bv.y; a12 += x1*bv.z; a13 += x1*bv.w;
    }
    float* Cp = g_part + kc*65536;
    *reinterpret_cast<float4*>(Cp + (rt*32+i0  )*512 + ct*64 + j0) = make_float4(a00,a01,a02,a03);
    *reinterpret_cast<float4*>(Cp + (rt*32+i0+1)*512 + ct*64 + j0) = make_float4(a10,a11,a12,a13);
}

__global__ void reduce4_kernel(int mode)
{
    int i = blockIdx.x*256 + threadIdx.x;
    float v = g_part[i] + g_part[i+65536] + g_part[i+131072] + g_part[i+196608];
    (mode ? g_featD : g_feat)[i] = v;
}

// ---------------------------------------------------------------------------
// Encoder: per-batch block (4 blocks, 1024 threads). Dynamic smem = feat (64KB).
// Computes attn (-> causal_graph), masks, inv(I-A), e/s/W_main, fU.
// ---------------------------------------------------------------------------
__global__ __launch_bounds__(1024) void enc_kernel(
    const float* __restrict__ adj, const float* __restrict__ asrc, const float* __restrict__ adst,
    const float* __restrict__ fce_w, const float* __restrict__ fce_b,
    const float* __restrict__ fcs_w, const float* __restrict__ fcs_b,
    const float* __restrict__ eps_main, float* __restrict__ out)
{
    extern __shared__ float Fs[];                  // 32 x 512
    __shared__ float At[32][33];
    __shared__ float Ms[32][33];
    __shared__ float ss[32], dd[32];
    __shared__ unsigned pm[32];
    int b = blockIdx.x;
    int t = threadIdx.x, w = t >> 5, lane = t & 31;

    #pragma unroll
    for (int it = 0; it < 4; ++it) {
        int l4 = t + 1024*it;
        reinterpret_cast<float4*>(Fs)[l4] = reinterpret_cast<const float4*>(g_feat + b*16384)[l4];
    }
    __syncthreads();

    // per-row dot products with a_src / a_dst (warp w <-> row w)
    {
        float s1 = 0.f, s2 = 0.f;
        #pragma unroll
        for (int c = 0; c < 16; ++c) {
            float f = Fs[w*512 + lane + 32*c];
            s1 += f * asrc[lane + 32*c];
            s2 += f * adst[lane + 32*c];
        }
        for (int o = 16; o; o >>= 1) {
            s1 += __shfl_xor_sync(0xffffffffu, s1, o);
            s2 += __shfl_xor_sync(0xffffffffu, s2, o);
        }
        if (lane == 0) { ss[w] = s1; dd[w] = s2; }
    }
    __syncthreads();

    // attn row w (masked softmax over strict-lower & adj>0)
    {
        int i = w, j = lane;
        float sc = ss[i] + dd[j];
        float lr = sc > 0.f ? sc : 0.2f*sc;
        bool valid = (adj[b*1024 + i*32 + j] > 0.f) && (j < i);
        float m = valid ? lr : -1e9f;
        float mx = m;
        for (int o = 16; o; o >>= 1) mx = fmaxf(mx, __shfl_xor_sync(0xffffffffu, mx, o));
        float p = expf(m - mx);
        float sum = p;
        for (int o = 16; o; o >>= 1) sum += __shfl_xor_sync(0xffffffffu, sum, o);
        float av = valid ? p/sum : 0.f;
        At[i][j] = av;
        g_attn[b*1024 + i*32 + j] = av;
        out[OFF_CG + b*1024 + i*32 + j] = av;       // causal_graph == attn
        unsigned bal = __ballot_sync(0xffffffffu, av > 0.f);
        if (lane == 0) pm[i] = bal;
    }
    __syncthreads();

    // common-cause bitmask: common[i][j] = (pm[i] & pm[j]) != 0
    {
        unsigned cm = __ballot_sync(0xffffffffu, (pm[w] & pm[lane]) != 0u);
        if (lane == 0) { g_posmask[b*32+w] = pm[w]; g_commonmask[b*32+w] = cm; }
    }
    __syncthreads();

    // inv(I - attn) by forward substitution: M = I + A*M (exact structural zeros)
    if (w == 0) {
        int j = lane;
        for (int i = 0; i < 32; ++i) {
            float v = (i == j) ? 1.f : 0.f;
            for (int k = 0; k < i; ++k) v += At[i][k] * Ms[k][j];
            Ms[i][j] = v;
        }
    }
    __syncthreads();

    // e, s, W_main
    {
        float few = fce_w[0], feb = fce_b[0], fsw = fcs_w[0], fsb = fcs_b[0];
        int i = t >> 5, j = t & 31;
        float iv = Ms[i][j];
        float ev = few*iv + feb;
        float sv = fsw*iv + fsb;
        out[OFF_E + b*1024 + t] = ev;
        out[OFF_S + b*1024 + t] = sv;
        g_Wmain[b*1024 + t] = (iv == 0.f) ? 0.f : ev + expf(0.5f*sv)*eps_main[b*1024 + t];
    }

    // fU = relu(attn @ feat)
    {
        int jg = t & 127, rg = t >> 7;
        float acc[4][4] = {};
        for (int k = 0; k < 32; ++k) {
            float4 f = reinterpret_cast<const float4*>(Fs + k*512)[jg];
            #pragma unroll
            for (int r = 0; r < 4; ++r) {
                float wv = At[rg + 8*r][k];
                acc[r][0] += wv*f.x; acc[r][1] += wv*f.y;
                acc[r][2] += wv*f.z; acc[r][3] += wv*f.w;
            }
        }
        #pragma unroll
        for (int r = 0; r < 4; ++r) {
            int i = rg + 8*r;
            float4 o = make_float4(fmaxf(acc[r][0],0.f), fmaxf(acc[r][1],0.f),
                                   fmaxf(acc[r][2],0.f), fmaxf(acc[r][3],0.f));
            reinterpret_cast<float4*>(g_fU + b*16384 + i*512)[jg] = o;
        }
    }
}

// ---------------------------------------------------------------------------
// X_raw = relu(W_main @ featD). grid (8 coltiles, 4 batches), 256 threads.
// ---------------------------------------------------------------------------
__global__ __launch_bounds__(256) void xraw_kernel(float* __restrict__ out)
{
    __shared__ float Ws[32][33];
    __shared__ float Ft[32][64];
    int ct = blockIdx.x, b = blockIdx.y;
    int t = threadIdx.x;

    for (int e = t; e < 1024; e += 256) Ws[e>>5][e&31] = g_Wmain[b*1024 + e];
    #pragma unroll
    for (int it = 0; it < 2; ++it) {
        int l4 = t + 256*it;
        int k = l4 >> 4, c4 = l4 & 15;
        *reinterpret_cast<float4*>(&Ft[k][c4*4]) =
            *reinterpret_cast<const float4*>(g_featD + b*16384 + k*512 + ct*64 + c4*4);
    }
    __syncthreads();

    int jg = t & 15, rg = t >> 4;
    float a0[4] = {}, a1[4] = {};
    for (int k = 0; k < 32; ++k) {
        float4 f = *reinterpret_cast<const float4*>(&Ft[k][jg*4]);
        float w0 = Ws[rg][k], w1 = Ws[rg+16][k];
        a0[0]+=w0*f.x; a0[1]+=w0*f.y; a0[2]+=w0*f.z; a0[3]+=w0*f.w;
        a1[0]+=w1*f.x; a1[1]+=w1*f.y; a1[2]+=w1*f.z; a1[3]+=w1*f.w;
    }
    *reinterpret_cast<float4*>(out + OFF_XRAW + b*16384 + rg*512 + ct*64 + jg*4) =
        make_float4(fmaxf(a0[0],0.f),fmaxf(a0[1],0.f),fmaxf(a0[2],0.f),fmaxf(a0[3],0.f));
    *reinterpret_cast<float4*>(out + OFF_XRAW + b*16384 + (rg+16)*512 + ct*64 + jg*4) =
        make_float4(fmaxf(a1[0],0.f),fmaxf(a1[1],0.f),fmaxf(a1[2],0.f),fmaxf(a1[3],0.f));
}

// ---------------------------------------------------------------------------
// Main do-intervention kernel: 1984 blocks, 512 threads, 64KB dyn smem (featD[b]).
// Per block: inv(I + A_zeroed) fwd-subst, W_do, label, X_do = relu(W_do @ featD).
// ---------------------------------------------------------------------------
__global__ void __launch_bounds__(512, 2) do_kernel(
    const float* __restrict__ eps_do,
    const float* __restrict__ fce_w, const float* __restrict__ fce_b,
    const float* __restrict__ fcs_w, const float* __restrict__ fcs_b,
    float* __restrict__ out)
{
    extern __shared__ float Fsh[];                 // 32 x 512
    __shared__ float At[32][33];
    __shared__ float Minv[32][33];
    __shared__ float Wdo[32][33];
    int bd = blockIdx.x;
    int b = bd / DOP, d = bd - b*DOP;
    int pa = 0, rem = d;
    while (rem >= NN-1-pa) { rem -= NN-1-pa; ++pa; }
    int pb = pa + 1 + rem;
    int t = threadIdx.x;

    #pragma unroll
    for (int it = 0; it < 8; ++it) {
        int l4 = t + 512*it;
        reinterpret_cast<float4*>(Fsh)[l4] = reinterpret_cast<const float4*>(g_featD + b*16384)[l4];
    }
    for (int e = t; e < 1024; e += 512) At[e>>5][e&31] = g_attn[b*1024 + e];
    __syncthreads();

    // inv(I + Az) with rows pa,pb of attn zeroed: M = I - Az*M  (exact zeros kept)
    if (t < 32) {
        int j = t;
        for (int i = 0; i < 32; ++i) {
            float v = (i == j) ? 1.f : 0.f;
            if (i != pa && i != pb)
                for (int k = 0; k < i; ++k) v -= At[i][k] * Minv[k][j];
            Minv[i][j] = v;
        }
    }
    __syncthreads();

    float few = fce_w[0], feb = fce_b[0], fsw = fcs_w[0], fsb = fcs_b[0];
    for (int e = t; e < 1024; e += 512) {
        int i = e >> 5, j = e & 31;
        float iv = Minv[i][j];
        float wv = 0.f;
        if (iv != 0.f)
            wv = few*iv + feb + expf(0.5f*(fsw*iv + fsb)) * eps_do[(size_t)bd*1024 + e];
        Wdo[i][j] = wv;
        // label
        bool lower = j < i;
        bool c23 = lower && ((j==pa && i!=pb) || (j==pb && i!=pa));
        bool c4  = lower && (j!=pa) && (j!=pb) && (i!=pa) && (i!=pb);
        bool pos = (g_posmask[b*32+i]    >> j) & 1u;
        bool com = (g_commonmask[b*32+i] >> j) & 1u;
        bool lab = (i==j) || (c23 && pos) || (c4 && com);
        out[OFF_LBL + (size_t)bd*1024 + e] = lab ? 1.f : 0.f;
    }
    __syncthreads();

    // X_do = relu(Wdo @ Fsh): thread tile 4 rows x 8 cols
    int jg = t & 63, rg = t >> 6;
    float acc[4][8];
    #pragma unroll
    for (int r = 0; r < 4; ++r)
        #pragma unroll
        for (int c = 0; c < 8; ++c) acc[r][c] = 0.f;
    for (int k = 0; k < 32; ++k) {
        float4 f0 = reinterpret_cast<const float4*>(Fsh + k*512)[jg*2];
        float4 f1 = reinterpret_cast<const float4*>(Fsh + k*512)[jg*2+1];
        #pragma unroll
        for (int r = 0; r < 4; ++r) {
            float wv = Wdo[rg + 8*r][k];
            acc[r][0]+=wv*f0.x; acc[r][1]+=wv*f0.y; acc[r][2]+=wv*f0.z; acc[r][3]+=wv*f0.w;
            acc[r][4]+=wv*f1.x; acc[r][5]+=wv*f1.y; acc[r][6]+=wv*f1.z; acc[r][7]+=wv*f1.w;
        }
    }
    float* ob = out + OFF_XDO + (size_t)bd*16384;
    #pragma unroll
    for (int r = 0; r < 4; ++r) {
        int i = rg + 8*r;
        reinterpret_cast<float4*>(ob + i*512)[jg*2] =
            make_float4(fmaxf(acc[r][0],0.f),fmaxf(acc[r][1],0.f),fmaxf(acc[r][2],0.f),fmaxf(acc[r][3],0.f));
        reinterpret_cast<float4*>(ob + i*512)[jg*2+1] =
            make_float4(fmaxf(acc[r][4],0.f),fmaxf(acc[r][5],0.f),fmaxf(acc[r][6],0.f),fmaxf(acc[r][7],0.f));
    }
}

// ---------------------------------------------------------------------------
extern "C" void kernel_launch(void* const* d_in, const int* in_sizes, int n_in,
                              void* d_out, int out_size)
{
    const float* h     = (const float*)d_in[0];
    const float* adj   = (const float*)d_in[1];
    // d_in[2] = doc_len (unused)
    const float* encWt = (const float*)d_in[3];
    const float* asrc  = (const float*)d_in[4];
    const float* adst  = (const float*)d_in[5];
    const float* decWt = (const float*)d_in[6];
    const float* fce_w = (const float*)d_in[7];
    const float* fce_b = (const float*)d_in[8];
    const float* fcs_w = (const float*)d_in[9];
    const float* fcs_b = (const float*)d_in[10];
    const float* eps_m = (const float*)d_in[11];
    const float* eps_d = (const float*)d_in[12];
    float* out = (float*)d_out;

    cudaFuncSetAttribute(enc_kernel, cudaFuncAttributeMaxDynamicSharedMemorySize, 65536);
    cudaFuncSetAttribute(do_kernel,  cudaFuncAttributeMaxDynamicSharedMemorySize, 65536);

    // feat = h @ enc_Wt
    gemm_part_kernel<<<dim3(8,4,4), 256>>>(h, encWt, 0);
    reduce4_kernel<<<256, 256>>>(0);
    // encoder: attn, masks, inv, e/s/W_main, fU
    enc_kernel<<<4, 1024, 65536>>>(adj, asrc, adst, fce_w, fce_b, fcs_w, fcs_b, eps_m, out);
    // featD = fU @ dec_Wt  (shared by X_raw and all 1984 X_do)
    gemm_part_kernel<<<dim3(8,4,4), 256>>>(nullptr, decWt, 1);
    reduce4_kernel<<<256, 256>>>(1);
    // X_raw
    xraw_kernel<<<dim3(8,4), 256>>>(out);
    // the big one: 1984 do-interventions
    do_kernel<<<BD, 512, 65536>>>(eps_d, fce_w, fce_b, fcs_w, fcs_b, out);
}

// round 3
// speedup vs baseline: 1.5983x; 1.5983x over previous
#include <cuda_runtime.h>
#include <math.h>

#define Bsz  4
#define NN   32
#define EMB  512
#define FEAT 512
#define DOP  496
#define BD   (Bsz*DOP)   // 1984

// output layout: concatenation of (X_raw, X_do, label, causal_graph, e, s)
#define OFF_XRAW 0
#define OFF_XDO  65536
#define OFF_LBL  32571392
#define OFF_CG   34603008
#define OFF_E    34607104
#define OFF_S    34611200

// scratch (no allocations allowed -> __device__ globals)
__device__ float    g_feat [Bsz*NN*FEAT];
__device__ float    g_fU   [Bsz*NN*FEAT];
__device__ float    g_featD[Bsz*NN*FEAT];
__device__ float    g_part [8*128*512];
__device__ float    g_attn [Bsz*NN*NN];
__device__ float    g_Wmain[Bsz*NN*NN];
__device__ unsigned g_posmask[Bsz*NN];
__device__ unsigned g_commonmask[Bsz*NN];

// packed fp32x2 FMA (SASS FFMA2) — ptxas never emits this from C++;
// 2x fp32 FMA throughput per issue slot on sm_103a.
__device__ __forceinline__ void ffma2(float2 &c, float2 a, float2 b) {
    asm("fma.rn.f32x2 %0, %1, %2, %0;"
        : "+l"(reinterpret_cast<unsigned long long&>(c))
        : "l"(reinterpret_cast<unsigned long long&>(a)),
          "l"(reinterpret_cast<unsigned long long&>(b)));
}

// ---------------------------------------------------------------------------
// C(128x512) = A(128x512) @ Bm(512x512), split-K into 8 chunks of 64.
// grid (8 ct, 4 rt, 8 kc), 256 threads. Tile 32x64 per block.
// mode 0: A = Aext (doc_sents_h) ; mode 1: A = g_fU
// ---------------------------------------------------------------------------
__global__ __launch_bounds__(256) void gemm_part_kernel(
    const float* __restrict__ Aext, const float* __restrict__ Bm, int mode)
{
    __shared__ float As[32][68];   // 68*4=272B row stride: 16B-aligned rows
    __shared__ float Bs[64][64];
    const float* A = mode ? g_fU : Aext;
    int ct = blockIdx.x, rt = blockIdx.y, kc = blockIdx.z;
    int t = threadIdx.x;

    #pragma unroll
    for (int it = 0; it < 2; ++it) {
        int l4 = t + 256*it;                 // 512 float4 total (32x64)
        int r = l4 >> 4, c4 = l4 & 15;
        float4 v = *reinterpret_cast<const float4*>(A + (rt*32 + r)*512 + kc*64 + c4*4);
        *reinterpret_cast<float4*>(&As[r][c4*4]) = v;
    }
    #pragma unroll
    for (int it = 0; it < 4; ++it) {
        int l4 = t + 256*it;                 // 1024 float4 total (64x64)
        int kk = l4 >> 4, c4 = l4 & 15;
        *reinterpret_cast<float4*>(&Bs[kk][c4*4]) =
            *reinterpret_cast<const float4*>(Bm + (kc*64 + kk)*512 + ct*64 + c4*4);
    }
    __syncthreads();

    int c4 = t & 15, r2 = t >> 4;
    int i0 = r2*2, j0 = c4*4;
    float2 p00 = {0.f,0.f}, p01 = {0.f,0.f}, p10 = {0.f,0.f}, p11 = {0.f,0.f};
    #pragma unroll 8
    for (int kk = 0; kk < 64; ++kk) {
        float4 bv = *reinterpret_cast<const float4*>(&Bs[kk][j0]);
        float2 b01 = make_float2(bv.x, bv.y), b23 = make_float2(bv.z, bv.w);
        float x0 = As[i0][kk], x1 = As[i0+1][kk];
        ffma2(p00, make_float2(x0,x0), b01);
        ffma2(p01, make_float2(x0,x0), b23);
        ffma2(p10, make_float2(x1,x1), b01);
        ffma2(p11, make_float2(x1,x1), b23);
    }
    float* Cp = g_part + kc*65536;
    *reinterpret_cast<float4*>(Cp + (rt*32+i0  )*512 + ct*64 + j0) = make_float4(p00.x,p00.y,p01.x,p01.y);
    *reinterpret_cast<float4*>(Cp + (rt*32+i0+1)*512 + ct*64 + j0) = make_float4(p10.x,p10.y,p11.x,p11.y);
}

__global__ void reduce8_kernel(int mode)
{
    int i = blockIdx.x*256 + threadIdx.x;
    float v = 0.f;
    #pragma unroll
    for (int c = 0; c < 8; ++c) v += g_part[i + c*65536];
    (mode ? g_featD : g_feat)[i] = v;
}

// ---------------------------------------------------------------------------
// Encoder: per-batch block (4 blocks, 1024 threads). Dynamic smem = feat (64KB).
// ---------------------------------------------------------------------------
__global__ __launch_bounds__(1024) void enc_kernel(
    const float* __restrict__ adj, const float* __restrict__ asrc, const float* __restrict__ adst,
    const float* __restrict__ fce_w, const float* __restrict__ fce_b,
    const float* __restrict__ fcs_w, const float* __restrict__ fcs_b,
    const float* __restrict__ eps_main, float* __restrict__ out)
{
    extern __shared__ float Fs[];                  // 32 x 512
    __shared__ float At[32][33];
    __shared__ float Ms[32][33];
    __shared__ float ss[32], dd[32];
    __shared__ unsigned pm[32];
    int b = blockIdx.x;
    int t = threadIdx.x, w = t >> 5, lane = t & 31;

    #pragma unroll
    for (int it = 0; it < 4; ++it) {
        int l4 = t + 1024*it;
        reinterpret_cast<float4*>(Fs)[l4] = reinterpret_cast<const float4*>(g_feat + b*16384)[l4];
    }
    __syncthreads();

    {
        float s1 = 0.f, s2 = 0.f;
        #pragma unroll
        for (int c = 0; c < 16; ++c) {
            float f = Fs[w*512 + lane + 32*c];
            s1 += f * asrc[lane + 32*c];
            s2 += f * adst[lane + 32*c];
        }
        for (int o = 16; o; o >>= 1) {
            s1 += __shfl_xor_sync(0xffffffffu, s1, o);
            s2 += __shfl_xor_sync(0xffffffffu, s2, o);
        }
        if (lane == 0) { ss[w] = s1; dd[w] = s2; }
    }
    __syncthreads();

    {
        int i = w, j = lane;
        float sc = ss[i] + dd[j];
        float lr = sc > 0.f ? sc : 0.2f*sc;
        bool valid = (adj[b*1024 + i*32 + j] > 0.f) && (j < i);
        float m = valid ? lr : -1e9f;
        float mx = m;
        for (int o = 16; o; o >>= 1) mx = fmaxf(mx, __shfl_xor_sync(0xffffffffu, mx, o));
        float p = expf(m - mx);
        float sum = p;
        for (int o = 16; o; o >>= 1) sum += __shfl_xor_sync(0xffffffffu, sum, o);
        float av = valid ? p/sum : 0.f;
        At[i][j] = av;
        g_attn[b*1024 + i*32 + j] = av;
        out[OFF_CG + b*1024 + i*32 + j] = av;
        unsigned bal = __ballot_sync(0xffffffffu, av > 0.f);
        if (lane == 0) pm[i] = bal;
    }
    __syncthreads();

    {
        unsigned cm = __ballot_sync(0xffffffffu, (pm[w] & pm[lane]) != 0u);
        if (lane == 0) { g_posmask[b*32+w] = pm[w]; g_commonmask[b*32+w] = cm; }
    }
    __syncthreads();

    // inv(I - attn) forward substitution, column j register-resident
    if (w == 0) {
        int j = lane;
        float Mc[32];
        #pragma unroll
        for (int i = 0; i < 32; ++i) {
            float v = (i == j) ? 1.f : 0.f;
            #pragma unroll
            for (int k = 0; k < i; ++k) v += At[i][k] * Mc[k];
            Mc[i] = v;
            Ms[i][j] = v;
        }
    }
    __syncthreads();

    {
        float few = fce_w[0], feb = fce_b[0], fsw = fcs_w[0], fsb = fcs_b[0];
        int i = t >> 5, j = t & 31;
        float iv = Ms[i][j];
        float ev = few*iv + feb;
        float sv = fsw*iv + fsb;
        out[OFF_E + b*1024 + t] = ev;
        out[OFF_S + b*1024 + t] = sv;
        g_Wmain[b*1024 + t] = (iv == 0.f) ? 0.f : ev + expf(0.5f*sv)*eps_main[b*1024 + t];
    }

    // fU = relu(attn @ feat)
    {
        int jg = t & 127, rg = t >> 7;
        float2 acc[4][2];
        #pragma unroll
        for (int r = 0; r < 4; ++r) { acc[r][0] = make_float2(0.f,0.f); acc[r][1] = make_float2(0.f,0.f); }
        for (int k = 0; k < 32; ++k) {
            float4 f = reinterpret_cast<const float4*>(Fs + k*512)[jg];
            float2 f01 = make_float2(f.x,f.y), f23 = make_float2(f.z,f.w);
            #pragma unroll
            for (int r = 0; r < 4; ++r) {
                float wv = At[rg + 8*r][k];
                ffma2(acc[r][0], make_float2(wv,wv), f01);
                ffma2(acc[r][1], make_float2(wv,wv), f23);
            }
        }
        #pragma unroll
        for (int r = 0; r < 4; ++r) {
            int i = rg + 8*r;
            float4 o = make_float4(fmaxf(acc[r][0].x,0.f), fmaxf(acc[r][0].y,0.f),
                                   fmaxf(acc[r][1].x,0.f), fmaxf(acc[r][1].y,0.f));
            reinterpret_cast<float4*>(g_fU + b*16384 + i*512)[jg] = o;
        }
    }
}

// ---------------------------------------------------------------------------
// X_raw = relu(W_main @ featD). grid (8 coltiles, 4 batches), 256 threads.
// ---------------------------------------------------------------------------
__global__ __launch_bounds__(256) void xraw_kernel(float* __restrict__ out)
{
    __shared__ float Ws[32][33];
    __shared__ float Ft[32][64];
    int ct = blockIdx.x, b = blockIdx.y;
    int t = threadIdx.x;

    for (int e = t; e < 1024; e += 256) Ws[e>>5][e&31] = g_Wmain[b*1024 + e];
    #pragma unroll
    for (int it = 0; it < 2; ++it) {
        int l4 = t + 256*it;
        int k = l4 >> 4, c4 = l4 & 15;
        *reinterpret_cast<float4*>(&Ft[k][c4*4]) =
            *reinterpret_cast<const float4*>(g_featD + b*16384 + k*512 + ct*64 + c4*4);
    }
    __syncthreads();

    int jg = t & 15, rg = t >> 4;
    float2 a0[2] = {{0.f,0.f},{0.f,0.f}}, a1[2] = {{0.f,0.f},{0.f,0.f}};
    #pragma unroll 4
    for (int k = 0; k < 32; ++k) {
        float4 f = *reinterpret_cast<const float4*>(&Ft[k][jg*4]);
        float2 f01 = make_float2(f.x,f.y), f23 = make_float2(f.z,f.w);
        float w0 = Ws[rg][k], w1 = Ws[rg+16][k];
        ffma2(a0[0], make_float2(w0,w0), f01);
        ffma2(a0[1], make_float2(w0,w0), f23);
        ffma2(a1[0], make_float2(w1,w1), f01);
        ffma2(a1[1], make_float2(w1,w1), f23);
    }
    *reinterpret_cast<float4*>(out + OFF_XRAW + b*16384 + rg*512 + ct*64 + jg*4) =
        make_float4(fmaxf(a0[0].x,0.f),fmaxf(a0[0].y,0.f),fmaxf(a0[1].x,0.f),fmaxf(a0[1].y,0.f));
    *reinterpret_cast<float4*>(out + OFF_XRAW + b*16384 + (rg+16)*512 + ct*64 + jg*4) =
        make_float4(fmaxf(a1[0].x,0.f),fmaxf(a1[0].y,0.f),fmaxf(a1[1].x,0.f),fmaxf(a1[1].y,0.f));
}

// ---------------------------------------------------------------------------
// Main do-intervention kernel: 1984 blocks, 512 threads, 64KB dyn smem.
// ---------------------------------------------------------------------------
__global__ void __launch_bounds__(512, 2) do_kernel(
    const float* __restrict__ eps_do,
    const float* __restrict__ fce_w, const float* __restrict__ fce_b,
    const float* __restrict__ fcs_w, const float* __restrict__ fcs_b,
    float* __restrict__ out)
{
    extern __shared__ float Fsh[];                 // 32 x 512
    __shared__ float At[32][33];
    __shared__ float Minv[32][33];
    __shared__ float Wdo[32][33];
    int bd = blockIdx.x;
    int b = bd / DOP, d = bd - b*DOP;
    int pa = 0, rem = d;
    while (rem >= NN-1-pa) { rem -= NN-1-pa; ++pa; }
    int pb = pa + 1 + rem;
    int t = threadIdx.x;

    #pragma unroll
    for (int it = 0; it < 8; ++it) {
        int l4 = t + 512*it;
        reinterpret_cast<float4*>(Fsh)[l4] = reinterpret_cast<const float4*>(g_featD + b*16384)[l4];
    }
    for (int e = t; e < 1024; e += 512) At[e>>5][e&31] = g_attn[b*1024 + e];
    __syncthreads();

    // inv(I + Az) with rows pa,pb zeroed: column j register-resident.
    // Structural zeros are exact: every term is a product with a 0 factor.
    if (t < 32) {
        const int j = t;
        float Mc[32];
        #pragma unroll
        for (int i = 0; i < 32; ++i) {
            float v = (i == j) ? 1.f : 0.f;
            if (i != pa && i != pb) {
                float v2 = 0.f;
                #pragma unroll
                for (int k = 0; k + 1 < i; k += 2) {
                    v  -= At[i][k]   * Mc[k];
                    v2 -= At[i][k+1] * Mc[k+1];
                }
                if (i & 1) v -= At[i][i-1] * Mc[i-1];
                v += v2;
            }
            Mc[i] = v;
            Minv[i][j] = v;
        }
    }
    __syncthreads();

    float few = fce_w[0], feb = fce_b[0], fsw = fcs_w[0], fsb = fcs_b[0];
    for (int e = t; e < 1024; e += 512) {
        int i = e >> 5, j = e & 31;
        float iv = Minv[i][j];
        float wv = 0.f;
        if (iv != 0.f)
            wv = few*iv + feb + expf(0.5f*(fsw*iv + fsb)) * eps_do[(size_t)bd*1024 + e];
        Wdo[i][j] = wv;
        bool lower = j < i;
        bool c23 = lower && ((j==pa && i!=pb) || (j==pb && i!=pa));
        bool c4  = lower && (j!=pa) && (j!=pb) && (i!=pa) && (i!=pb);
        bool pos = (g_posmask[b*32+i]    >> j) & 1u;
        bool com = (g_commonmask[b*32+i] >> j) & 1u;
        bool lab = (i==j) || (c23 && pos) || (c4 && com);
        out[OFF_LBL + (size_t)bd*1024 + e] = lab ? 1.f : 0.f;
    }
    __syncthreads();

    // X_do = relu(Wdo @ Fsh): 8 rows x 4 cols per thread, FFMA2 inner.
    int jg = t & 127, rg = t >> 7;    // jg: float4 column group; rg: 0..3
    float2 acc[8][2];
    #pragma unroll
    for (int r = 0; r < 8; ++r) { acc[r][0] = make_float2(0.f,0.f); acc[r][1] = make_float2(0.f,0.f); }
    const float4* F4 = reinterpret_cast<const float4*>(Fsh);
    #pragma unroll 4
    for (int k = 0; k < 32; ++k) {
        float4 f = F4[k*128 + jg];
        float2 f01 = make_float2(f.x,f.y), f23 = make_float2(f.z,f.w);
        #pragma unroll
        for (int r = 0; r < 8; ++r) {
            float wv = Wdo[rg + 4*r][k];
            ffma2(acc[r][0], make_float2(wv,wv), f01);
            ffma2(acc[r][1], make_float2(wv,wv), f23);
        }
    }
    float* ob = out + OFF_XDO + (size_t)bd*16384;
    #pragma unroll
    for (int r = 0; r < 8; ++r) {
        int i = rg + 4*r;
        reinterpret_cast<float4*>(ob + i*512)[jg] =
            make_float4(fmaxf(acc[r][0].x,0.f), fmaxf(acc[r][0].y,0.f),
                        fmaxf(acc[r][1].x,0.f), fmaxf(acc[r][1].y,0.f));
    }
}

// ---------------------------------------------------------------------------
extern "C" void kernel_launch(void* const* d_in, const int* in_sizes, int n_in,
                              void* d_out, int out_size)
{
    const float* h     = (const float*)d_in[0];
    const float* adj   = (const float*)d_in[1];
    const float* encWt = (const float*)d_in[3];
    const float* asrc  = (const float*)d_in[4];
    const float* adst  = (const float*)d_in[5];
    const float* decWt = (const float*)d_in[6];
    const float* fce_w = (const float*)d_in[7];
    const float* fce_b = (const float*)d_in[8];
    const float* fcs_w = (const float*)d_in[9];
    const float* fcs_b = (const float*)d_in[10];
    const float* eps_m = (const float*)d_in[11];
    const float* eps_d = (const float*)d_in[12];
    float* out = (float*)d_out;

    cudaFuncSetAttribute(enc_kernel, cudaFuncAttributeMaxDynamicSharedMemorySize, 65536);
    cudaFuncSetAttribute(do_kernel,  cudaFuncAttributeMaxDynamicSharedMemorySize, 65536);

    gemm_part_kernel<<<dim3(8,4,8), 256>>>(h, encWt, 0);
    reduce8_kernel<<<256, 256>>>(0);
    enc_kernel<<<4, 1024, 65536>>>(adj, asrc, adst, fce_w, fce_b, fcs_w, fcs_b, eps_m, out);
    gemm_part_kernel<<<dim3(8,4,8), 256>>>(nullptr, decWt, 1);
    reduce8_kernel<<<256, 256>>>(1);
    xraw_kernel<<<dim3(8,4), 256>>>(out);
    do_kernel<<<BD, 512, 65536>>>(eps_d, fce_w, fce_b, fcs_w, fcs_b, out);
}